// round 3
// baseline (speedup 1.0000x reference)
#include <cuda_runtime.h>
#include <math.h>

// Problem constants
#define B_ 4
#define T_ 4096
#define C_ 512
#define H_ 64
#define SCALE 8.0f   // sqrt(64), MULTIPLIED into scores per reference

// Intermediate q,k,v buffers: [B, T, H] fp32 each (4 MB each)
__device__ float g_q[B_ * T_ * H_];
__device__ float g_k[B_ * T_ * H_];
__device__ float g_v[B_ * T_ * H_];

// ---------------------------------------------------------------------------
// Packed fp32x2 helpers (Blackwell dual-fp32 pipe; ptxas never auto-fuses)
// ---------------------------------------------------------------------------
typedef unsigned long long u64t;

__device__ __forceinline__ u64t fma2(u64t a, u64t b, u64t c) {
    u64t d;
    asm("fma.rn.f32x2 %0, %1, %2, %3;" : "=l"(d) : "l"(a), "l"(b), "l"(c));
    return d;
}
__device__ __forceinline__ u64t mul2(u64t a, u64t b) {
    u64t d;
    asm("mul.rn.f32x2 %0, %1, %2;" : "=l"(d) : "l"(a), "l"(b));
    return d;
}
__device__ __forceinline__ u64t pack2(float x, float y) {
    u64t d;
    unsigned xi = __float_as_uint(x), yi = __float_as_uint(y);
    asm("mov.b64 %0, {%1, %2};" : "=l"(d) : "r"(xi), "r"(yi));
    return d;
}
__device__ __forceinline__ float hadd2(u64t a) {
    unsigned lo, hi;
    asm("mov.b64 {%0, %1}, %2;" : "=r"(lo), "=r"(hi) : "l"(a));
    return __uint_as_float(lo) + __uint_as_float(hi);
}

// ---------------------------------------------------------------------------
// Kernel 1: QKV projection.  out = x @ W for W in {Wq, Wk, Wv} (blockIdx.y).
// M = B*T = 16384, K = 512, N = 64.  Block tile 64x64, K-chunk 64,
// 256 threads, 4x4 register tile, contraction packed in f32x2 pairs.
// Xs [m][c] pitch 68 (broadcast LDS.64 reads); Wt [n][c] pitch 66
// (transposed on store; reads at n = tx+16j hit banks 2*tx -> conflict-free).
// q is pre-scaled by SCALE so attention scores come out already scaled.
// ---------------------------------------------------------------------------
__global__ __launch_bounds__(256) void qkv_kernel(
    const float* __restrict__ x,
    const float* __restrict__ Wq,
    const float* __restrict__ Wk,
    const float* __restrict__ Wv)
{
    __shared__ float Xs[64][68];
    __shared__ float Wt[64][66];   // [n][c]

    const int tx = threadIdx.x;          // 0..15
    const int ty = threadIdx.y;          // 0..15
    const int tid = ty * 16 + tx;

    const float* W;
    float* outp;
    float oscale;
    if (blockIdx.y == 0)      { W = Wq; outp = g_q; oscale = SCALE; }
    else if (blockIdx.y == 1) { W = Wk; outp = g_k; oscale = 1.0f; }
    else                      { W = Wv; outp = g_v; oscale = 1.0f; }

    const int m0 = blockIdx.x * 64;

    // Per-thread tile-load mapping: f = tid + i*256, r = f>>4, c4 = (f&15)*4
    float4 xr[4], wr[4];
#pragma unroll
    for (int i = 0; i < 4; i++) {
        int f = tid + i * 256;
        int r = f >> 4, c = (f & 15) * 4;
        xr[i] = *(const float4*)&x[(size_t)(m0 + r) * C_ + c];
        wr[i] = *(const float4*)&W[(size_t)r * H_ + c];
    }

    u64t acc[4][4];
#pragma unroll
    for (int i = 0; i < 4; i++)
#pragma unroll
        for (int j = 0; j < 4; j++) acc[i][j] = 0ull;

    for (int c0 = 0; c0 < C_; c0 += 64) {
        __syncthreads();
#pragma unroll
        for (int i = 0; i < 4; i++) {
            int f = tid + i * 256;
            int r = f >> 4, c = (f & 15) * 4;
            *(float4*)&Xs[r][c] = xr[i];
            // Wt transpose: wr[i] is W[c-dim r][n-dim c..c+3]
            Wt[c + 0][r] = wr[i].x;
            Wt[c + 1][r] = wr[i].y;
            Wt[c + 2][r] = wr[i].z;
            Wt[c + 3][r] = wr[i].w;
        }
        __syncthreads();

        if (c0 + 64 < C_) {
            int cn = c0 + 64;
#pragma unroll
            for (int i = 0; i < 4; i++) {
                int f = tid + i * 256;
                int r = f >> 4, c = (f & 15) * 4;
                xr[i] = *(const float4*)&x[(size_t)(m0 + r) * C_ + cn + c];
                wr[i] = *(const float4*)&W[(size_t)(cn + r) * H_ + c];
            }
        }

#pragma unroll 8
        for (int c2 = 0; c2 < 32; c2++) {
            u64t a0 = *(const u64t*)&Xs[ty * 4 + 0][2 * c2];
            u64t a1 = *(const u64t*)&Xs[ty * 4 + 1][2 * c2];
            u64t a2 = *(const u64t*)&Xs[ty * 4 + 2][2 * c2];
            u64t a3 = *(const u64t*)&Xs[ty * 4 + 3][2 * c2];
            u64t b0 = *(const u64t*)&Wt[tx +  0][2 * c2];
            u64t b1 = *(const u64t*)&Wt[tx + 16][2 * c2];
            u64t b2 = *(const u64t*)&Wt[tx + 32][2 * c2];
            u64t b3 = *(const u64t*)&Wt[tx + 48][2 * c2];
            acc[0][0] = fma2(a0, b0, acc[0][0]); acc[0][1] = fma2(a0, b1, acc[0][1]);
            acc[0][2] = fma2(a0, b2, acc[0][2]); acc[0][3] = fma2(a0, b3, acc[0][3]);
            acc[1][0] = fma2(a1, b0, acc[1][0]); acc[1][1] = fma2(a1, b1, acc[1][1]);
            acc[1][2] = fma2(a1, b2, acc[1][2]); acc[1][3] = fma2(a1, b3, acc[1][3]);
            acc[2][0] = fma2(a2, b0, acc[2][0]); acc[2][1] = fma2(a2, b1, acc[2][1]);
            acc[2][2] = fma2(a2, b2, acc[2][2]); acc[2][3] = fma2(a2, b3, acc[2][3]);
            acc[3][0] = fma2(a3, b0, acc[3][0]); acc[3][1] = fma2(a3, b1, acc[3][1]);
            acc[3][2] = fma2(a3, b2, acc[3][2]); acc[3][3] = fma2(a3, b3, acc[3][3]);
        }
    }

    // Epilogue: out[m][n], n = tx + 16*j (coalesced scalar stores)
#pragma unroll
    for (int i = 0; i < 4; i++) {
        int m = m0 + ty * 4 + i;
#pragma unroll
        for (int j = 0; j < 4; j++)
            outp[(size_t)m * H_ + tx + 16 * j] = hadd2(acc[i][j]) * oscale;
    }
}

// ---------------------------------------------------------------------------
// Kernel 2: flash attention (no causal mask), fp32x2-packed, online softmax.
// Grid: (T/64, B).  Block: 256 threads (16x16), occ 2.  Q tile = 64 queries,
// K tile = 64 keys/step, 64 steps, next tile register-prefetched.
// Smem:
//   Qs [qi][kk]  pitch 68   broadcast LDS.64 reads along kk pairs
//   Ks [kj][kk]  pitch 66   natural; reads at kj = tx+16j -> banks 2*tx, CF
//   Vt [d][kj]   pitch 66   transposed on store; reads at d = tx+16j, CF
//   Ps [qi][kj]  pitch 68   probabilities; scalar scatter, pair reads
// Thread (ty,tx): qi = 4*ty+i, key/out column = tx + 16*j.
// ---------------------------------------------------------------------------
__global__ __launch_bounds__(256, 2) void attn_kernel(float* __restrict__ out)
{
    extern __shared__ float sm[];
    float* Qs = sm;                    // 64*68
    float* Ks = Qs + 64 * 68;          // 64*66
    float* Vt = Ks + 64 * 66;          // 64*66
    float* Ps = Vt + 64 * 66;          // 64*68

    const int tx = threadIdx.x;
    const int ty = threadIdx.y;
    const int tid = ty * 16 + tx;
    const int b = blockIdx.y;
    const int q0 = blockIdx.x * 64;

    const float* Qg = g_q + ((size_t)b * T_ + q0) * H_;
    const float* Kg = g_k + (size_t)b * T_ * H_;
    const float* Vg = g_v + (size_t)b * T_ * H_;

    // Load Q tile once (float4, pitch 68 keeps 16B row alignment)
#pragma unroll
    for (int i = 0; i < 4; i++) {
        int f = tid + i * 256;
        int r = f >> 4, c = (f & 15) * 4;
        *(float4*)&Qs[r * 68 + c] = *(const float4*)&Qg[(size_t)r * H_ + c];
    }

    // Prefetch first K/V tile into registers
    float4 kreg[4], vreg[4];
#pragma unroll
    for (int i = 0; i < 4; i++) {
        int f = tid + i * 256;
        int r = f >> 4, c = (f & 15) * 4;
        kreg[i] = *(const float4*)&Kg[(size_t)r * H_ + c];
        vreg[i] = *(const float4*)&Vg[(size_t)r * H_ + c];
    }

    float m_run[4], l_run[4];
    u64t O_pk[4][4];
#pragma unroll
    for (int i = 0; i < 4; i++) {
        m_run[i] = -INFINITY;
        l_run[i] = 0.0f;
#pragma unroll
        for (int j = 0; j < 4; j++) O_pk[i][j] = 0ull;
    }

    for (int s0 = 0; s0 < T_; s0 += 64) {
        __syncthreads();   // previous PV done with Vt/Ps (no-op first iter)

        // Store prefetched K (natural, float2 pairs) and V (transposed)
#pragma unroll
        for (int i = 0; i < 4; i++) {
            int f = tid + i * 256;
            int r = f >> 4, c = (f & 15) * 4;
            *(float2*)&Ks[r * 66 + c]     = make_float2(kreg[i].x, kreg[i].y);
            *(float2*)&Ks[r * 66 + c + 2] = make_float2(kreg[i].z, kreg[i].w);
            Vt[(c + 0) * 66 + r] = vreg[i].x;
            Vt[(c + 1) * 66 + r] = vreg[i].y;
            Vt[(c + 2) * 66 + r] = vreg[i].z;
            Vt[(c + 3) * 66 + r] = vreg[i].w;
        }
        __syncthreads();

        // Prefetch next tile (latency overlaps QK + softmax + PV)
        if (s0 + 64 < T_) {
            const float* Kn = Kg + (size_t)(s0 + 64) * H_;
            const float* Vn = Vg + (size_t)(s0 + 64) * H_;
#pragma unroll
            for (int i = 0; i < 4; i++) {
                int f = tid + i * 256;
                int r = f >> 4, c = (f & 15) * 4;
                kreg[i] = *(const float4*)&Kn[(size_t)r * H_ + c];
                vreg[i] = *(const float4*)&Vn[(size_t)r * H_ + c];
            }
        }

        // S = Q K^T, packed along kk (q already carries the x8 scale)
        u64t s_pk[4][4];
#pragma unroll
        for (int i = 0; i < 4; i++)
#pragma unroll
            for (int j = 0; j < 4; j++) s_pk[i][j] = 0ull;

#pragma unroll 8
        for (int k2 = 0; k2 < 32; k2++) {
            u64t a0 = *(const u64t*)&Qs[(ty * 4 + 0) * 68 + 2 * k2];
            u64t a1 = *(const u64t*)&Qs[(ty * 4 + 1) * 68 + 2 * k2];
            u64t a2 = *(const u64t*)&Qs[(ty * 4 + 2) * 68 + 2 * k2];
            u64t a3 = *(const u64t*)&Qs[(ty * 4 + 3) * 68 + 2 * k2];
            u64t b0 = *(const u64t*)&Ks[(tx +  0) * 66 + 2 * k2];
            u64t b1 = *(const u64t*)&Ks[(tx + 16) * 66 + 2 * k2];
            u64t b2 = *(const u64t*)&Ks[(tx + 32) * 66 + 2 * k2];
            u64t b3 = *(const u64t*)&Ks[(tx + 48) * 66 + 2 * k2];
            s_pk[0][0] = fma2(a0, b0, s_pk[0][0]); s_pk[0][1] = fma2(a0, b1, s_pk[0][1]);
            s_pk[0][2] = fma2(a0, b2, s_pk[0][2]); s_pk[0][3] = fma2(a0, b3, s_pk[0][3]);
            s_pk[1][0] = fma2(a1, b0, s_pk[1][0]); s_pk[1][1] = fma2(a1, b1, s_pk[1][1]);
            s_pk[1][2] = fma2(a1, b2, s_pk[1][2]); s_pk[1][3] = fma2(a1, b3, s_pk[1][3]);
            s_pk[2][0] = fma2(a2, b0, s_pk[2][0]); s_pk[2][1] = fma2(a2, b1, s_pk[2][1]);
            s_pk[2][2] = fma2(a2, b2, s_pk[2][2]); s_pk[2][3] = fma2(a2, b3, s_pk[2][3]);
            s_pk[3][0] = fma2(a3, b0, s_pk[3][0]); s_pk[3][1] = fma2(a3, b1, s_pk[3][1]);
            s_pk[3][2] = fma2(a3, b2, s_pk[3][2]); s_pk[3][3] = fma2(a3, b3, s_pk[3][3]);
        }

        // Online softmax; s[i][j] is score for query 4ty+i, key s0 + tx + 16j
#pragma unroll
        for (int i = 0; i < 4; i++) {
            float sv[4];
#pragma unroll
            for (int j = 0; j < 4; j++) sv[j] = hadd2(s_pk[i][j]);

            float lm = fmaxf(fmaxf(sv[0], sv[1]), fmaxf(sv[2], sv[3]));
#pragma unroll
            for (int off = 8; off >= 1; off >>= 1)
                lm = fmaxf(lm, __shfl_xor_sync(0xFFFFFFFFu, lm, off));
            float mn = fmaxf(m_run[i], lm);
            float f = __expf(m_run[i] - mn);
            m_run[i] = mn;

            float p0 = __expf(sv[0] - mn);
            float p1 = __expf(sv[1] - mn);
            float p2 = __expf(sv[2] - mn);
            float p3 = __expf(sv[3] - mn);
            float ls = (p0 + p1) + (p2 + p3);
#pragma unroll
            for (int off = 8; off >= 1; off >>= 1)
                ls += __shfl_xor_sync(0xFFFFFFFFu, ls, off);
            l_run[i] = l_run[i] * f + ls;

            u64t fp = pack2(f, f);
#pragma unroll
            for (int j = 0; j < 4; j++) O_pk[i][j] = mul2(O_pk[i][j], fp);

            int prow = (ty * 4 + i) * 68;
            Ps[prow + tx +  0] = p0;
            Ps[prow + tx + 16] = p1;
            Ps[prow + tx + 32] = p2;
            Ps[prow + tx + 48] = p3;
        }
        __syncthreads();

        // O += P V, packed along kj.  O_pk[i][j]: output dim d = tx + 16j.
#pragma unroll 8
        for (int k2 = 0; k2 < 32; k2++) {
            u64t p0 = *(const u64t*)&Ps[(ty * 4 + 0) * 68 + 2 * k2];
            u64t p1 = *(const u64t*)&Ps[(ty * 4 + 1) * 68 + 2 * k2];
            u64t p2 = *(const u64t*)&Ps[(ty * 4 + 2) * 68 + 2 * k2];
            u64t p3 = *(const u64t*)&Ps[(ty * 4 + 3) * 68 + 2 * k2];
            u64t v0 = *(const u64t*)&Vt[(tx +  0) * 66 + 2 * k2];
            u64t v1 = *(const u64t*)&Vt[(tx + 16) * 66 + 2 * k2];
            u64t v2 = *(const u64t*)&Vt[(tx + 32) * 66 + 2 * k2];
            u64t v3 = *(const u64t*)&Vt[(tx + 48) * 66 + 2 * k2];
            O_pk[0][0] = fma2(p0, v0, O_pk[0][0]); O_pk[0][1] = fma2(p0, v1, O_pk[0][1]);
            O_pk[0][2] = fma2(p0, v2, O_pk[0][2]); O_pk[0][3] = fma2(p0, v3, O_pk[0][3]);
            O_pk[1][0] = fma2(p1, v0, O_pk[1][0]); O_pk[1][1] = fma2(p1, v1, O_pk[1][1]);
            O_pk[1][2] = fma2(p1, v2, O_pk[1][2]); O_pk[1][3] = fma2(p1, v3, O_pk[1][3]);
            O_pk[2][0] = fma2(p2, v0, O_pk[2][0]); O_pk[2][1] = fma2(p2, v1, O_pk[2][1]);
            O_pk[2][2] = fma2(p2, v2, O_pk[2][2]); O_pk[2][3] = fma2(p2, v3, O_pk[2][3]);
            O_pk[3][0] = fma2(p3, v0, O_pk[3][0]); O_pk[3][1] = fma2(p3, v1, O_pk[3][1]);
            O_pk[3][2] = fma2(p3, v2, O_pk[3][2]); O_pk[3][3] = fma2(p3, v3, O_pk[3][3]);
        }
    }

    // Epilogue: normalize and store [B, T, H]; d = tx + 16j (coalesced)
#pragma unroll
    for (int i = 0; i < 4; i++) {
        float inv = 1.0f / l_run[i];
        int t = q0 + ty * 4 + i;
        float* orow = out + ((size_t)b * T_ + t) * H_;
#pragma unroll
        for (int j = 0; j < 4; j++)
            orow[tx + 16 * j] = hadd2(O_pk[i][j]) * inv;
    }
}

// ---------------------------------------------------------------------------
// Launch
// ---------------------------------------------------------------------------
extern "C" void kernel_launch(void* const* d_in, const int* in_sizes, int n_in,
                              void* d_out, int out_size)
{
    (void)in_sizes; (void)n_in; (void)out_size;
    const float* x  = (const float*)d_in[0];
    const float* Wq = (const float*)d_in[1];
    const float* Wk = (const float*)d_in[2];
    const float* Wv = (const float*)d_in[3];
    float* out = (float*)d_out;

    // QKV projection: (M/64, 3) blocks
    dim3 g1((B_ * T_) / 64, 3);
    dim3 blk(16, 16);
    qkv_kernel<<<g1, blk>>>(x, Wq, Wk, Wv);

    // Flash attention: (T/64, B) blocks, 68608 B dynamic smem
    const int smem_bytes = (64 * 68 + 64 * 66 + 64 * 66 + 64 * 68) * (int)sizeof(float);
    cudaFuncSetAttribute(attn_kernel,
                         cudaFuncAttributeMaxDynamicSharedMemorySize, smem_bytes);
    dim3 g2(T_ / 64, B_);
    attn_kernel<<<g2, blk, smem_bytes>>>(out);
}

// round 5
// speedup vs baseline: 1.0793x; 1.0793x over previous
#include <cuda_runtime.h>
#include <math.h>

// Problem constants
#define B_ 4
#define T_ 4096
#define C_ 512
#define H_ 64
#define SCALE 8.0f   // sqrt(64), MULTIPLIED into scores per reference

// Intermediate q,k,v buffers: [B, T, H] fp32 each (4 MB each)
__device__ float g_q[B_ * T_ * H_];
__device__ float g_k[B_ * T_ * H_];
__device__ float g_v[B_ * T_ * H_];

// ---------------------------------------------------------------------------
// Packed fp32x2 helpers (Blackwell dual-fp32 pipe; ptxas never auto-fuses)
// ---------------------------------------------------------------------------
typedef unsigned long long u64t;

__device__ __forceinline__ u64t fma2(u64t a, u64t b, u64t c) {
    u64t d;
    asm("fma.rn.f32x2 %0, %1, %2, %3;" : "=l"(d) : "l"(a), "l"(b), "l"(c));
    return d;
}
__device__ __forceinline__ u64t mul2(u64t a, u64t b) {
    u64t d;
    asm("mul.rn.f32x2 %0, %1, %2;" : "=l"(d) : "l"(a), "l"(b));
    return d;
}
__device__ __forceinline__ u64t pack2(float x, float y) {
    u64t d;
    unsigned xi = __float_as_uint(x), yi = __float_as_uint(y);
    asm("mov.b64 %0, {%1, %2};" : "=l"(d) : "r"(xi), "r"(yi));
    return d;
}
__device__ __forceinline__ float hadd2(u64t a) {
    unsigned lo, hi;
    asm("mov.b64 {%0, %1}, %2;" : "=r"(lo), "=r"(hi) : "l"(a));
    return __uint_as_float(lo) + __uint_as_float(hi);
}
__device__ __forceinline__ u64t d2u(double x) { return (u64t)__double_as_longlong(x); }

// ---------------------------------------------------------------------------
// Kernel 1: QKV projection (verified pass in R3, ~100us).
// out = x @ W for W in {Wq, Wk, Wv} (blockIdx.y). M=16384, K=512, N=64.
// ---------------------------------------------------------------------------
__global__ __launch_bounds__(256) void qkv_kernel(
    const float* __restrict__ x,
    const float* __restrict__ Wq,
    const float* __restrict__ Wk,
    const float* __restrict__ Wv)
{
    __shared__ float Xs[64][68];
    __shared__ float Wt[64][66];   // [n][c]

    const int tx = threadIdx.x;          // 0..15
    const int ty = threadIdx.y;          // 0..15
    const int tid = ty * 16 + tx;

    const float* W;
    float* outp;
    float oscale;
    if (blockIdx.y == 0)      { W = Wq; outp = g_q; oscale = SCALE; }
    else if (blockIdx.y == 1) { W = Wk; outp = g_k; oscale = 1.0f; }
    else                      { W = Wv; outp = g_v; oscale = 1.0f; }

    const int m0 = blockIdx.x * 64;

    float4 xr[4], wr[4];
#pragma unroll
    for (int i = 0; i < 4; i++) {
        int f = tid + i * 256;
        int r = f >> 4, c = (f & 15) * 4;
        xr[i] = *(const float4*)&x[(size_t)(m0 + r) * C_ + c];
        wr[i] = *(const float4*)&W[(size_t)r * H_ + c];
    }

    u64t acc[4][4];
#pragma unroll
    for (int i = 0; i < 4; i++)
#pragma unroll
        for (int j = 0; j < 4; j++) acc[i][j] = 0ull;

    for (int c0 = 0; c0 < C_; c0 += 64) {
        __syncthreads();
#pragma unroll
        for (int i = 0; i < 4; i++) {
            int f = tid + i * 256;
            int r = f >> 4, c = (f & 15) * 4;
            *(float4*)&Xs[r][c] = xr[i];
            Wt[c + 0][r] = wr[i].x;
            Wt[c + 1][r] = wr[i].y;
            Wt[c + 2][r] = wr[i].z;
            Wt[c + 3][r] = wr[i].w;
        }
        __syncthreads();

        if (c0 + 64 < C_) {
            int cn = c0 + 64;
#pragma unroll
            for (int i = 0; i < 4; i++) {
                int f = tid + i * 256;
                int r = f >> 4, c = (f & 15) * 4;
                xr[i] = *(const float4*)&x[(size_t)(m0 + r) * C_ + cn + c];
                wr[i] = *(const float4*)&W[(size_t)(cn + r) * H_ + c];
            }
        }

#pragma unroll 8
        for (int c2 = 0; c2 < 32; c2++) {
            u64t a0 = *(const u64t*)&Xs[ty * 4 + 0][2 * c2];
            u64t a1 = *(const u64t*)&Xs[ty * 4 + 1][2 * c2];
            u64t a2 = *(const u64t*)&Xs[ty * 4 + 2][2 * c2];
            u64t a3 = *(const u64t*)&Xs[ty * 4 + 3][2 * c2];
            u64t b0 = *(const u64t*)&Wt[tx +  0][2 * c2];
            u64t b1 = *(const u64t*)&Wt[tx + 16][2 * c2];
            u64t b2 = *(const u64t*)&Wt[tx + 32][2 * c2];
            u64t b3 = *(const u64t*)&Wt[tx + 48][2 * c2];
            acc[0][0] = fma2(a0, b0, acc[0][0]); acc[0][1] = fma2(a0, b1, acc[0][1]);
            acc[0][2] = fma2(a0, b2, acc[0][2]); acc[0][3] = fma2(a0, b3, acc[0][3]);
            acc[1][0] = fma2(a1, b0, acc[1][0]); acc[1][1] = fma2(a1, b1, acc[1][1]);
            acc[1][2] = fma2(a1, b2, acc[1][2]); acc[1][3] = fma2(a1, b3, acc[1][3]);
            acc[2][0] = fma2(a2, b0, acc[2][0]); acc[2][1] = fma2(a2, b1, acc[2][1]);
            acc[2][2] = fma2(a2, b2, acc[2][2]); acc[2][3] = fma2(a2, b3, acc[2][3]);
            acc[3][0] = fma2(a3, b0, acc[3][0]); acc[3][1] = fma2(a3, b1, acc[3][1]);
            acc[3][2] = fma2(a3, b2, acc[3][2]); acc[3][3] = fma2(a3, b3, acc[3][3]);
        }
    }

#pragma unroll
    for (int i = 0; i < 4; i++) {
        int m = m0 + ty * 4 + i;
#pragma unroll
        for (int j = 0; j < 4; j++)
            outp[(size_t)m * H_ + tx + 16 * j] = hadd2(acc[i][j]) * oscale;
    }
}

// ---------------------------------------------------------------------------
// Kernel 2: flash attention, fp32x2, retiled 8x4 register tiles.
// Grid: (T/64, B).  Block: 128 threads (tx=16, ty=8).
// Per thread: QK  -> qi = ty+8i (8 rows) x kj = tx+16jj (4 keys)
//             PV  -> qi = ty+8i (8 rows) x d  = 4tx+dd  (4 dims)
// Smem (floats):
//   Qs [64][68]  natural;     .128 reads, 2 rows/warp -> broadcast, 1 wf
//   Ks [64][68]  natural;     .128 reads, 16 addrs stride 68 -> CF, 2 wf
//   Vt [64][64]  transposed,  col kj ^ (d&28) XOR swizzle:
//                scalar transpose-stores 2-way, .128 reads CF 2 wf
//   Ps [64][68]  natural;     scalar stores 2 wf, .128 bcast reads 1 wf
// Ratio: 16 wf per 64 fma2-inst per m-iter -> LDS no longer binding.
// ---------------------------------------------------------------------------
__global__ __launch_bounds__(128) void attn_kernel(float* __restrict__ out)
{
    extern __shared__ float sm[];
    float* Qs = sm;                    // 64*68
    float* Ks = Qs + 64 * 68;          // 64*68
    float* Vt = Ks + 64 * 68;          // 64*64
    float* Ps = Vt + 64 * 64;          // 64*68

    const int tx = threadIdx.x;        // 0..15
    const int ty = threadIdx.y;        // 0..7
    const int tid = ty * 16 + tx;      // 0..127
    const int b = blockIdx.y;
    const int q0 = blockIdx.x * 64;

    const float* Qg = g_q + ((size_t)b * T_ + q0) * H_;
    const float* Kg = g_k + (size_t)b * T_ * H_;
    const float* Vg = g_v + (size_t)b * T_ * H_;

    // Load Q tile once: 8 float4 per thread
#pragma unroll
    for (int t = 0; t < 8; t++) {
        int f = tid + t * 128;
        int r = f >> 4, c = (f & 15) * 4;
        *(float4*)&Qs[r * 68 + c] = *(const float4*)&Qg[(size_t)r * H_ + c];
    }

    float m_run[8], l_run[8];
    u64t O_pk[8][4];                   // [qi][d = 4tx+dd], packed along kj
#pragma unroll
    for (int i = 0; i < 8; i++) {
        m_run[i] = -INFINITY;
        l_run[i] = 0.0f;
#pragma unroll
        for (int dd = 0; dd < 4; dd++) O_pk[i][dd] = 0ull;
    }

    for (int s0 = 0; s0 < T_; s0 += 64) {
        __syncthreads();   // prev step's Ks/Vt/Ps reads complete

        // ---- Load K tile -> Ks (natural, pitch 68) ----
        {
            float4 kv[8];
#pragma unroll
            for (int t = 0; t < 8; t++) {
                int f = tid + t * 128;
                int r = f >> 4, c = (f & 15) * 4;
                kv[t] = *(const float4*)&Kg[(size_t)(s0 + r) * H_ + c];
            }
#pragma unroll
            for (int t = 0; t < 8; t++) {
                int f = tid + t * 128;
                int r = f >> 4, c = (f & 15) * 4;
                *(float4*)&Ks[r * 68 + c] = kv[t];
            }
        }
        // ---- Load V tile -> Vt (transposed, XOR swizzled) ----
        {
            float4 vv[8];
#pragma unroll
            for (int t = 0; t < 8; t++) {
                int f = tid + t * 128;
                int r = f >> 4, c = (f & 15) * 4;
                vv[t] = *(const float4*)&Vg[(size_t)(s0 + r) * H_ + c];
            }
#pragma unroll
            for (int t = 0; t < 8; t++) {
                int f = tid + t * 128;
                int r = f >> 4, c = (f & 15) * 4;   // r = kj, c..c+3 = d
                Vt[(c + 0) * 64 + (r ^ ((c + 0) & 28))] = vv[t].x;
                Vt[(c + 1) * 64 + (r ^ ((c + 1) & 28))] = vv[t].y;
                Vt[(c + 2) * 64 + (r ^ ((c + 2) & 28))] = vv[t].z;
                Vt[(c + 3) * 64 + (r ^ ((c + 3) & 28))] = vv[t].w;
            }
        }
        __syncthreads();

        // ---- S = Q K^T, packed along kk (q carries the x8 scale) ----
        u64t s_pk[8][4];
#pragma unroll
        for (int i = 0; i < 8; i++)
#pragma unroll
            for (int jj = 0; jj < 4; jj++) s_pk[i][jj] = 0ull;

#pragma unroll
        for (int m = 0; m < 16; m++) {
            double2 a[8];
#pragma unroll
            for (int i = 0; i < 8; i++)
                a[i] = *(const double2*)&Qs[(ty + 8 * i) * 68 + 4 * m];
            double2 bv[4];
#pragma unroll
            for (int jj = 0; jj < 4; jj++)
                bv[jj] = *(const double2*)&Ks[(tx + 16 * jj) * 68 + 4 * m];
#pragma unroll
            for (int i = 0; i < 8; i++)
#pragma unroll
                for (int jj = 0; jj < 4; jj++) {
                    s_pk[i][jj] = fma2(d2u(a[i].x), d2u(bv[jj].x), s_pk[i][jj]);
                    s_pk[i][jj] = fma2(d2u(a[i].y), d2u(bv[jj].y), s_pk[i][jj]);
                }
        }

        // ---- Online softmax (reduce across the 16 tx lanes) ----
#pragma unroll
        for (int i = 0; i < 8; i++) {
            float sv0 = hadd2(s_pk[i][0]);
            float sv1 = hadd2(s_pk[i][1]);
            float sv2 = hadd2(s_pk[i][2]);
            float sv3 = hadd2(s_pk[i][3]);

            float lm = fmaxf(fmaxf(sv0, sv1), fmaxf(sv2, sv3));
#pragma unroll
            for (int off = 8; off >= 1; off >>= 1)
                lm = fmaxf(lm, __shfl_xor_sync(0xFFFFFFFFu, lm, off));
            float mn = fmaxf(m_run[i], lm);
            float f = __expf(m_run[i] - mn);
            m_run[i] = mn;

            float p0 = __expf(sv0 - mn);
            float p1 = __expf(sv1 - mn);
            float p2 = __expf(sv2 - mn);
            float p3 = __expf(sv3 - mn);
            float ls = (p0 + p1) + (p2 + p3);
#pragma unroll
            for (int off = 8; off >= 1; off >>= 1)
                ls += __shfl_xor_sync(0xFFFFFFFFu, ls, off);
            l_run[i] = l_run[i] * f + ls;

            u64t fp = pack2(f, f);
#pragma unroll
            for (int dd = 0; dd < 4; dd++) O_pk[i][dd] = mul2(O_pk[i][dd], fp);

            int prow = (ty + 8 * i) * 68;
            Ps[prow + tx +  0] = p0;
            Ps[prow + tx + 16] = p1;
            Ps[prow + tx + 32] = p2;
            Ps[prow + tx + 48] = p3;
        }
        __syncthreads();   // Ps visible to all

        // ---- O += P V, packed along kj ----
        // Vt read at base (4m)^(d&28): element t is V[4m+t][d] (bits 0-1
        // disjoint from XOR mask bits 2-4), matching Ps element kj=4m+t.
#pragma unroll
        for (int m = 0; m < 16; m++) {
            double2 p[8];
#pragma unroll
            for (int i = 0; i < 8; i++)
                p[i] = *(const double2*)&Ps[(ty + 8 * i) * 68 + 4 * m];
            double2 v[4];
#pragma unroll
            for (int dd = 0; dd < 4; dd++) {
                int d = 4 * tx + dd;
                v[dd] = *(const double2*)&Vt[d * 64 + ((4 * m) ^ (d & 28))];
            }
#pragma unroll
            for (int i = 0; i < 8; i++)
#pragma unroll
                for (int dd = 0; dd < 4; dd++) {
                    O_pk[i][dd] = fma2(d2u(p[i].x), d2u(v[dd].x), O_pk[i][dd]);
                    O_pk[i][dd] = fma2(d2u(p[i].y), d2u(v[dd].y), O_pk[i][dd]);
                }
        }
    }

    // Epilogue: normalize and store [B, T, H]; d = 4tx..4tx+3 (float4)
#pragma unroll
    for (int i = 0; i < 8; i++) {
        float inv = 1.0f / l_run[i];
        int t = q0 + ty + 8 * i;
        float4 o;
        o.x = hadd2(O_pk[i][0]) * inv;
        o.y = hadd2(O_pk[i][1]) * inv;
        o.z = hadd2(O_pk[i][2]) * inv;
        o.w = hadd2(O_pk[i][3]) * inv;
        *(float4*)&out[((size_t)b * T_ + t) * H_ + 4 * tx] = o;
    }
}

// ---------------------------------------------------------------------------
// Launch
// ---------------------------------------------------------------------------
extern "C" void kernel_launch(void* const* d_in, const int* in_sizes, int n_in,
                              void* d_out, int out_size)
{
    (void)in_sizes; (void)n_in; (void)out_size;
    const float* x  = (const float*)d_in[0];
    const float* Wq = (const float*)d_in[1];
    const float* Wk = (const float*)d_in[2];
    const float* Wv = (const float*)d_in[3];
    float* out = (float*)d_out;

    // QKV projection: (M/64, 3) blocks of 256 threads
    dim3 g1((B_ * T_) / 64, 3);
    qkv_kernel<<<g1, dim3(16, 16)>>>(x, Wq, Wk, Wv);

    // Flash attention: (T/64, B) blocks of 128 threads, 68608 B dynamic smem
    const int smem_bytes = (64 * 68 + 64 * 68 + 64 * 64 + 64 * 68) * (int)sizeof(float);
    cudaFuncSetAttribute(attn_kernel,
                         cudaFuncAttributeMaxDynamicSharedMemorySize, smem_bytes);
    dim3 g2(T_ / 64, B_);
    attn_kernel<<<g2, dim3(16, 8), smem_bytes>>>(out);
}

// round 15
// speedup vs baseline: 1.1328x; 1.0496x over previous
#include <cuda_runtime.h>
#include <math.h>

// Problem constants
#define B_ 4
#define T_ 4096
#define C_ 512
#define H_ 64
// q carries score scale sqrt(64)=8 AND log2(e) so softmax can use raw ex2.
#define QSCALE (8.0f * 1.4426950408889634f)

// Intermediates: q,k natural [B,T,H]; v transposed [B,H,T]
__device__ float g_q[B_ * T_ * H_];
__device__ float g_k[B_ * T_ * H_];
__device__ float g_vt[B_ * H_ * T_];

// ---------------------------------------------------------------------------
// Packed fp32x2 helpers (Blackwell dual-fp32 pipe; ptxas never auto-fuses)
// ---------------------------------------------------------------------------
typedef unsigned long long u64t;

__device__ __forceinline__ u64t fma2(u64t a, u64t b, u64t c) {
    u64t d;
    asm("fma.rn.f32x2 %0, %1, %2, %3;" : "=l"(d) : "l"(a), "l"(b), "l"(c));
    return d;
}
__device__ __forceinline__ u64t mul2(u64t a, u64t b) {
    u64t d;
    asm("mul.rn.f32x2 %0, %1, %2;" : "=l"(d) : "l"(a), "l"(b));
    return d;
}
__device__ __forceinline__ u64t pack2(float x, float y) {
    u64t d;
    unsigned xi = __float_as_uint(x), yi = __float_as_uint(y);
    asm("mov.b64 %0, {%1, %2};" : "=l"(d) : "r"(xi), "r"(yi));
    return d;
}
__device__ __forceinline__ float hadd2(u64t a) {
    unsigned lo, hi;
    asm("mov.b64 {%0, %1}, %2;" : "=r"(lo), "=r"(hi) : "l"(a));
    return __uint_as_float(lo) + __uint_as_float(hi);
}
__device__ __forceinline__ u64t d2u(double x) { return (u64t)__double_as_longlong(x); }
__device__ __forceinline__ float ex2f(float x) {
    float r;
    asm("ex2.approx.ftz.f32 %0, %1;" : "=f"(r) : "f"(x));
    return r;
}

// cp.async helpers
__device__ __forceinline__ void cpa16(unsigned dst, const void* src) {
    asm volatile("cp.async.cg.shared.global [%0], [%1], 16;" :: "r"(dst), "l"(src));
}
__device__ __forceinline__ void cpa_commit() { asm volatile("cp.async.commit_group;"); }
__device__ __forceinline__ void cpa_wait0()  { asm volatile("cp.async.wait_group 0;"); }

// ---------------------------------------------------------------------------
// Kernel 1: QKV projection. out = x @ W (blockIdx.y selects Q/K/V).
// q pre-scaled by 8*log2e; V written TRANSPOSED to g_vt[b][h][t].
// ---------------------------------------------------------------------------
__global__ __launch_bounds__(256) void qkv_kernel(
    const float* __restrict__ x,
    const float* __restrict__ Wq,
    const float* __restrict__ Wk,
    const float* __restrict__ Wv)
{
    __shared__ float Xs[64][68];
    __shared__ float Wt[64][66];   // [n][c]

    const int tx = threadIdx.x;          // 0..15
    const int ty = threadIdx.y;          // 0..15
    const int tid = ty * 16 + tx;

    const float* W;
    if (blockIdx.y == 0)      W = Wq;
    else if (blockIdx.y == 1) W = Wk;
    else                      W = Wv;

    const int m0 = blockIdx.x * 64;

    float4 xr[4], wr[4];
#pragma unroll
    for (int i = 0; i < 4; i++) {
        int f = tid + i * 256;
        int r = f >> 4, c = (f & 15) * 4;
        xr[i] = *(const float4*)&x[(size_t)(m0 + r) * C_ + c];
        wr[i] = *(const float4*)&W[(size_t)r * H_ + c];
    }

    u64t acc[4][4];
#pragma unroll
    for (int i = 0; i < 4; i++)
#pragma unroll
        for (int j = 0; j < 4; j++) acc[i][j] = 0ull;

    for (int c0 = 0; c0 < C_; c0 += 64) {
        __syncthreads();
#pragma unroll
        for (int i = 0; i < 4; i++) {
            int f = tid + i * 256;
            int r = f >> 4, c = (f & 15) * 4;
            *(float4*)&Xs[r][c] = xr[i];
            Wt[c + 0][r] = wr[i].x;
            Wt[c + 1][r] = wr[i].y;
            Wt[c + 2][r] = wr[i].z;
            Wt[c + 3][r] = wr[i].w;
        }
        __syncthreads();

        if (c0 + 64 < C_) {
            int cn = c0 + 64;
#pragma unroll
            for (int i = 0; i < 4; i++) {
                int f = tid + i * 256;
                int r = f >> 4, c = (f & 15) * 4;
                xr[i] = *(const float4*)&x[(size_t)(m0 + r) * C_ + cn + c];
                wr[i] = *(const float4*)&W[(size_t)(cn + r) * H_ + c];
            }
        }

#pragma unroll 8
        for (int c2 = 0; c2 < 32; c2++) {
            u64t a0 = *(const u64t*)&Xs[ty * 4 + 0][2 * c2];
            u64t a1 = *(const u64t*)&Xs[ty * 4 + 1][2 * c2];
            u64t a2 = *(const u64t*)&Xs[ty * 4 + 2][2 * c2];
            u64t a3 = *(const u64t*)&Xs[ty * 4 + 3][2 * c2];
            u64t b0 = *(const u64t*)&Wt[tx +  0][2 * c2];
            u64t b1 = *(const u64t*)&Wt[tx + 16][2 * c2];
            u64t b2 = *(const u64t*)&Wt[tx + 32][2 * c2];
            u64t b3 = *(const u64t*)&Wt[tx + 48][2 * c2];
            acc[0][0] = fma2(a0, b0, acc[0][0]); acc[0][1] = fma2(a0, b1, acc[0][1]);
            acc[0][2] = fma2(a0, b2, acc[0][2]); acc[0][3] = fma2(a0, b3, acc[0][3]);
            acc[1][0] = fma2(a1, b0, acc[1][0]); acc[1][1] = fma2(a1, b1, acc[1][1]);
            acc[1][2] = fma2(a1, b2, acc[1][2]); acc[1][3] = fma2(a1, b3, acc[1][3]);
            acc[2][0] = fma2(a2, b0, acc[2][0]); acc[2][1] = fma2(a2, b1, acc[2][1]);
            acc[2][2] = fma2(a2, b2, acc[2][2]); acc[2][3] = fma2(a2, b3, acc[2][3]);
            acc[3][0] = fma2(a3, b0, acc[3][0]); acc[3][1] = fma2(a3, b1, acc[3][1]);
            acc[3][2] = fma2(a3, b2, acc[3][2]); acc[3][3] = fma2(a3, b3, acc[3][3]);
        }
    }

    if (blockIdx.y == 2) {
        // V: write transposed g_vt[b][n][t]
        int b = m0 / T_;
        float* vt = g_vt + (size_t)b * H_ * T_;
#pragma unroll
        for (int i = 0; i < 4; i++) {
            int t = m0 - b * T_ + ty * 4 + i;
#pragma unroll
            for (int j = 0; j < 4; j++)
                vt[(size_t)(tx + 16 * j) * T_ + t] = hadd2(acc[i][j]);
        }
    } else {
        float* outp = (blockIdx.y == 0) ? g_q : g_k;
        float oscale = (blockIdx.y == 0) ? QSCALE : 1.0f;
#pragma unroll
        for (int i = 0; i < 4; i++) {
            int m = m0 + ty * 4 + i;
#pragma unroll
            for (int j = 0; j < 4; j++)
                outp[(size_t)m * H_ + tx + 16 * j] = hadd2(acc[i][j]) * oscale;
        }
    }
}

// ---------------------------------------------------------------------------
// Kernel 2: flash attention, fp32x2, 8x4 tiles, cp.async double-buffered K/V.
// Grid: (T/64, B).  Block: 128 threads (tx=16, ty=8), 2 CTAs/SM forced.
// Smem: Qs[64][68], Ps[64][68], 2 stages of { Ks[64][68], Vt[64][64] }.
// Vt cols XOR-swizzled: element (kj, d) at d*64 + (kj ^ (d&28)).
// V comes pre-transposed from gmem so cp.async lands it directly.
// ---------------------------------------------------------------------------
#define QS_OFF   0
#define PS_OFF   (64 * 68)
#define ST_OFF   (2 * 64 * 68)
#define ST_SIZE  (64 * 68 + 64 * 64)
#define KS_OFF(s) (ST_OFF + (s) * ST_SIZE)
#define VT_OFF(s) (ST_OFF + (s) * ST_SIZE + 64 * 68)
#define SMEM_FLOATS (2 * 64 * 68 + 2 * ST_SIZE)

__global__ __launch_bounds__(128, 2) void attn_kernel(float* __restrict__ out)
{
    extern __shared__ float sm[];
    float* Qs = sm + QS_OFF;
    float* Ps = sm + PS_OFF;

    const int tx = threadIdx.x;        // 0..15
    const int ty = threadIdx.y;        // 0..7
    const int tid = ty * 16 + tx;      // 0..127
    const int b = blockIdx.y;
    const int q0 = blockIdx.x * 64;

    const float* Qg  = g_q  + ((size_t)b * T_ + q0) * H_;
    const float* Kg  = g_k  + (size_t)b * T_ * H_;
    const float* Vgt = g_vt + (size_t)b * H_ * T_;

    const unsigned smem_base = (unsigned)__cvta_generic_to_shared(sm);

    // Issue stage 0 loads immediately (overlap with Q load below)
    {
#pragma unroll
        for (int t = 0; t < 8; t++) {
            int id = tid + t * 128;
            int r = id >> 4, c = (id & 15) * 4;
            cpa16(smem_base + (KS_OFF(0) + r * 68 + c) * 4, Kg + (size_t)r * H_ + c);
            cpa16(smem_base + (VT_OFF(0) + r * 64 + (c ^ (r & 28))) * 4,
                  Vgt + (size_t)r * T_ + c);
        }
        cpa_commit();
    }

    // Load Q tile once
#pragma unroll
    for (int t = 0; t < 8; t++) {
        int f = tid + t * 128;
        int r = f >> 4, c = (f & 15) * 4;
        *(float4*)&Qs[r * 68 + c] = *(const float4*)&Qg[(size_t)r * H_ + c];
    }

    float m_run[8], l_run[8];
    u64t O_pk[8][4];
#pragma unroll
    for (int i = 0; i < 8; i++) {
        m_run[i] = -INFINITY;
        l_run[i] = 0.0f;
#pragma unroll
        for (int dd = 0; dd < 4; dd++) O_pk[i][dd] = 0ull;
    }

    for (int step = 0; step < T_ / 64; step++) {
        const int sb = step & 1;
        float* Ks = sm + KS_OFF(sb);
        float* Vt = sm + VT_OFF(sb);

        cpa_wait0();        // stage `step` landed (this thread's copies)
        __syncthreads();    // all copies visible; prev PV done -> other buf free

        // Issue next stage into the other buffer (overlaps full compute step)
        if (step + 1 < T_ / 64) {
            const int s0n = (step + 1) * 64;
            const int nb = 1 - sb;
#pragma unroll
            for (int t = 0; t < 8; t++) {
                int id = tid + t * 128;
                int r = id >> 4, c = (id & 15) * 4;
                cpa16(smem_base + (KS_OFF(nb) + r * 68 + c) * 4,
                      Kg + (size_t)(s0n + r) * H_ + c);
                cpa16(smem_base + (VT_OFF(nb) + r * 64 + (c ^ (r & 28))) * 4,
                      Vgt + (size_t)r * T_ + s0n + c);
            }
            cpa_commit();
        }

        // ---- S = Q K^T, packed along kk (q carries 8*log2e scale) ----
        u64t s_pk[8][4];
#pragma unroll
        for (int i = 0; i < 8; i++)
#pragma unroll
            for (int jj = 0; jj < 4; jj++) s_pk[i][jj] = 0ull;

#pragma unroll
        for (int m = 0; m < 16; m++) {
            double2 a[8];
#pragma unroll
            for (int i = 0; i < 8; i++)
                a[i] = *(const double2*)&Qs[(ty + 8 * i) * 68 + 4 * m];
            double2 bv[4];
#pragma unroll
            for (int jj = 0; jj < 4; jj++)
                bv[jj] = *(const double2*)&Ks[(tx + 16 * jj) * 68 + 4 * m];
#pragma unroll
            for (int i = 0; i < 8; i++)
#pragma unroll
                for (int jj = 0; jj < 4; jj++) {
                    s_pk[i][jj] = fma2(d2u(a[i].x), d2u(bv[jj].x), s_pk[i][jj]);
                    s_pk[i][jj] = fma2(d2u(a[i].y), d2u(bv[jj].y), s_pk[i][jj]);
                }
        }

        // ---- Online softmax, phase-split for cross-row ILP ----
        float sv[8][4];
#pragma unroll
        for (int i = 0; i < 8; i++)
#pragma unroll
            for (int jj = 0; jj < 4; jj++) sv[i][jj] = hadd2(s_pk[i][jj]);

        float lm[8];
#pragma unroll
        for (int i = 0; i < 8; i++)
            lm[i] = fmaxf(fmaxf(sv[i][0], sv[i][1]), fmaxf(sv[i][2], sv[i][3]));
#pragma unroll
        for (int off = 8; off >= 1; off >>= 1)
#pragma unroll
            for (int i = 0; i < 8; i++)
                lm[i] = fmaxf(lm[i], __shfl_xor_sync(0xFFFFFFFFu, lm[i], off));

        float fs[8], ls[8];
#pragma unroll
        for (int i = 0; i < 8; i++) {
            float mn = fmaxf(m_run[i], lm[i]);
            fs[i] = ex2f(m_run[i] - mn);
            m_run[i] = mn;
            float p0 = ex2f(sv[i][0] - mn);
            float p1 = ex2f(sv[i][1] - mn);
            float p2 = ex2f(sv[i][2] - mn);
            float p3 = ex2f(sv[i][3] - mn);
            ls[i] = (p0 + p1) + (p2 + p3);
            int prow = (ty + 8 * i) * 68;
            Ps[prow + tx +  0] = p0;
            Ps[prow + tx + 16] = p1;
            Ps[prow + tx + 32] = p2;
            Ps[prow + tx + 48] = p3;
        }
#pragma unroll
        for (int off = 8; off >= 1; off >>= 1)
#pragma unroll
            for (int i = 0; i < 8; i++)
                ls[i] += __shfl_xor_sync(0xFFFFFFFFu, ls[i], off);
#pragma unroll
        for (int i = 0; i < 8; i++) {
            l_run[i] = l_run[i] * fs[i] + ls[i];
            u64t fp = pack2(fs[i], fs[i]);
#pragma unroll
            for (int dd = 0; dd < 4; dd++) O_pk[i][dd] = mul2(O_pk[i][dd], fp);
        }
        __syncthreads();   // Ps visible

        // ---- O += P V, packed along kj ----
#pragma unroll
        for (int m = 0; m < 16; m++) {
            double2 p[8];
#pragma unroll
            for (int i = 0; i < 8; i++)
                p[i] = *(const double2*)&Ps[(ty + 8 * i) * 68 + 4 * m];
            double2 v[4];
#pragma unroll
            for (int dd = 0; dd < 4; dd++) {
                int d = 4 * tx + dd;
                v[dd] = *(const double2*)&Vt[d * 64 + ((4 * m) ^ (d & 28))];
            }
#pragma unroll
            for (int i = 0; i < 8; i++)
#pragma unroll
                for (int dd = 0; dd < 4; dd++) {
                    O_pk[i][dd] = fma2(d2u(p[i].x), d2u(v[dd].x), O_pk[i][dd]);
                    O_pk[i][dd] = fma2(d2u(p[i].y), d2u(v[dd].y), O_pk[i][dd]);
                }
        }
    }

    // Epilogue: normalize and store [B, T, H]
#pragma unroll
    for (int i = 0; i < 8; i++) {
        float inv = 1.0f / l_run[i];
        int t = q0 + ty + 8 * i;
        float4 o;
        o.x = hadd2(O_pk[i][0]) * inv;
        o.y = hadd2(O_pk[i][1]) * inv;
        o.z = hadd2(O_pk[i][2]) * inv;
        o.w = hadd2(O_pk[i][3]) * inv;
        *(float4*)&out[((size_t)b * T_ + t) * H_ + 4 * tx] = o;
    }
}

// ---------------------------------------------------------------------------
// Launch
// ---------------------------------------------------------------------------
extern "C" void kernel_launch(void* const* d_in, const int* in_sizes, int n_in,
                              void* d_out, int out_size)
{
    (void)in_sizes; (void)n_in; (void)out_size;
    const float* x  = (const float*)d_in[0];
    const float* Wq = (const float*)d_in[1];
    const float* Wk = (const float*)d_in[2];
    const float* Wv = (const float*)d_in[3];
    float* out = (float*)d_out;

    dim3 g1((B_ * T_) / 64, 3);
    qkv_kernel<<<g1, dim3(16, 16)>>>(x, Wq, Wk, Wv);

    const int smem_bytes = SMEM_FLOATS * (int)sizeof(float);   // 102400 B
    cudaFuncSetAttribute(attn_kernel,
                         cudaFuncAttributeMaxDynamicSharedMemorySize, smem_bytes);
    dim3 g2(T_ / 64, B_);
    attn_kernel<<<g2, dim3(16, 8), smem_bytes>>>(out);
}